// round 1
// baseline (speedup 1.0000x reference)
#include <cuda_runtime.h>
#include <cuda_bf16.h>
#include <math.h>

// Problem constants
#define Hdim   3584
#define Bb     8
#define NH     28
#define KVH    4
#define GS     7
#define HD     128
#define MB     16
#define BSZ    256
#define Rr     32          // B*KVH
#define SCALE  0.08838834764831845f
#define NEG_INF (-1e30f)

// -------- scratch (device globals, no allocation) --------
__device__ float g_q_raw[Bb * Hdim];       // pre-rope q
__device__ float g_k_raw[Bb * KVH * HD];   // pre-rope k
__device__ float g_q[Bb * Hdim];           // post-rope q
__device__ float g_k[Bb * KVH * HD];       // post-rope k (k_new rows)
__device__ float g_v[Bb * KVH * HD];       // v_new rows
__device__ float g_part[Rr * MB * GS * HD];  // per-chunk partial PV sums
__device__ float g_ml[Rr * MB * GS * 2];     // per-chunk (m, l)
__device__ float g_attn[Bb * Hdim];          // attention output pre O-proj

// ============================================================
// gemv8: y[b][row] = dot(x[b], W[row]) + bias[row], for 8 batches
// one block per row, 128 threads, float4 loads.
// mode: 0 -> dst g_q_raw (stride 3584)
//       1 -> dst g_k_raw (stride 512)
//       2 -> dst g_v     (stride 512)
//       3 -> x = g_attn, dst = dstExt (stride 3584)
// ============================================================
__global__ void gemv8(const float* __restrict__ x,
                      const float* __restrict__ W,
                      const float* __restrict__ bias,
                      float* __restrict__ dstExt,
                      int mode) {
    const int row = blockIdx.x;
    const int t = threadIdx.x;      // 128 threads

    const float* xp = (mode == 3) ? g_attn : x;
    float* dst;
    int stride;
    if (mode == 0)      { dst = g_q_raw; stride = Hdim; }
    else if (mode == 1) { dst = g_k_raw; stride = KVH * HD; }
    else if (mode == 2) { dst = g_v;     stride = KVH * HD; }
    else                { dst = dstExt;  stride = Hdim; }

    const float4* __restrict__ w4 = (const float4*)(W + (size_t)row * Hdim);
    const float4* __restrict__ x4 = (const float4*)xp;

    float acc[8];
#pragma unroll
    for (int b = 0; b < 8; b++) acc[b] = 0.f;

#pragma unroll
    for (int it = 0; it < 7; it++) {
        const int c4 = t + it * 128;            // 0..895
        const float4 wv = w4[c4];
#pragma unroll
        for (int b = 0; b < 8; b++) {
            const float4 hv = x4[b * 896 + c4];
            acc[b] += wv.x * hv.x + wv.y * hv.y + wv.z * hv.z + wv.w * hv.w;
        }
    }

    const int lane = t & 31, warp = t >> 5;
#pragma unroll
    for (int b = 0; b < 8; b++) {
#pragma unroll
        for (int off = 16; off; off >>= 1)
            acc[b] += __shfl_xor_sync(0xffffffffu, acc[b], off);
    }
    __shared__ float red[4][8];
    if (lane == 0) {
#pragma unroll
        for (int b = 0; b < 8; b++) red[warp][b] = acc[b];
    }
    __syncthreads();
    if (t < 8) {
        float s = red[0][t] + red[1][t] + red[2][t] + red[3][t];
        if (bias) s += bias[row];
        dst[(size_t)t * stride + row] = s;
    }
}

// ============================================================
// RoPE: q (28 heads) and k (4 heads) per batch.
// grid = B*32 blocks, 128 threads (d).
// ============================================================
__global__ void rope_kernel(const float* __restrict__ cos_,
                            const float* __restrict__ sin_) {
    const int blk = blockIdx.x;
    const int b = blk >> 5;
    const int h = blk & 31;
    const int d = threadIdx.x;

    const float c = cos_[b * HD + d];
    const float s = sin_[b * HD + d];

    const float* src;
    float* dst;
    if (h < NH) {
        src = g_q_raw + (size_t)b * Hdim + h * HD;
        dst = g_q     + (size_t)b * Hdim + h * HD;
    } else {
        const int kv = h - NH;
        src = g_k_raw + (size_t)b * KVH * HD + kv * HD;
        dst = g_k     + (size_t)b * KVH * HD + kv * HD;
    }
    const float x = src[d];
    const float other = (d < 64) ? -src[d + 64] : src[d - 64];
    dst[d] = x * c + other * s;
}

// ============================================================
// Attention partial (flash-decode split-K).
// grid = (16 chunks, 32 rows), 256 threads.
// ============================================================
__global__ void attn_partial(const float* __restrict__ k_pool,
                             const float* __restrict__ v_pool,
                             const int* __restrict__ block_table,
                             const int* __restrict__ cache_seqlens) {
    const int c = blockIdx.x;
    const int r = blockIdx.y;
    const int seqlen = cache_seqlens[r];
    const int base = c * BSZ;
    if (base >= seqlen) return;

    const int nvalid = min(BSZ, seqlen - base);
    const int pos = seqlen - 1;
    const int jpos = pos - base;       // local index of the new token (may be out of [0,256))
    const int b = r >> 2;
    const int kvh = r & 3;
    const int blk = block_table[r * MB + c];
    const float* __restrict__ K = k_pool + (size_t)blk * BSZ * HD;
    const float* __restrict__ V = v_pool + (size_t)blk * BSZ * HD;

    __shared__ float q_s[GS][HD];
    __shared__ float p_s[GS][BSZ];
    __shared__ float knew_s[HD];
    __shared__ float vnew_s[HD];
    __shared__ float red_s[8];
    __shared__ float bc0;
    __shared__ float acc2_s[GS][HD];

    const int t = threadIdx.x;
    const float* qbase = g_q + (size_t)b * Hdim + kvh * GS * HD;
    for (int i = t; i < GS * HD; i += 256) ((float*)q_s)[i] = qbase[i];
    if (t < HD) {
        knew_s[t] = g_k[r * HD + t];
        vnew_s[t] = g_v[r * HD + t];
    }
    __syncthreads();

    // ---- phase 1: QK dots, one token per thread ----
    float sc[GS];
#pragma unroll
    for (int g = 0; g < GS; g++) sc[g] = 0.f;
    const int j = t;
    const bool valid = (j < nvalid);
    if (valid) {
        const float4* kp = (j == jpos) ? (const float4*)knew_s
                                       : (const float4*)(K + (size_t)j * HD);
#pragma unroll
        for (int d4 = 0; d4 < 32; d4++) {
            const float4 kv = kp[d4];
#pragma unroll
            for (int g = 0; g < GS; g++) {
                const float4 qv = ((const float4*)q_s[g])[d4];
                sc[g] += qv.x * kv.x + qv.y * kv.y + qv.z * kv.z + qv.w * kv.w;
            }
        }
    }

    // ---- phase 2: chunk-local softmax per head group ----
    const int lane = t & 31, warp = t >> 5;
    const int rc = r * MB + c;
    for (int g = 0; g < GS; g++) {
        const float v = valid ? sc[g] * SCALE : NEG_INF;
        float m = v;
#pragma unroll
        for (int off = 16; off; off >>= 1)
            m = fmaxf(m, __shfl_xor_sync(0xffffffffu, m, off));
        if (lane == 0) red_s[warp] = m;
        __syncthreads();
        if (t == 0) {
            float mm = red_s[0];
#pragma unroll
            for (int w = 1; w < 8; w++) mm = fmaxf(mm, red_s[w]);
            bc0 = mm;
        }
        __syncthreads();
        const float M = bc0;
        const float e = valid ? __expf(v - M) : 0.f;
        float l = e;
#pragma unroll
        for (int off = 16; off; off >>= 1)
            l += __shfl_xor_sync(0xffffffffu, l, off);
        if (lane == 0) red_s[warp] = l;
        p_s[g][t] = e;
        __syncthreads();
        if (t == 0) {
            float ll = 0.f;
#pragma unroll
            for (int w = 0; w < 8; w++) ll += red_s[w];
            g_ml[rc * (GS * 2) + g * 2 + 0] = M;
            g_ml[rc * (GS * 2) + g * 2 + 1] = ll;
        }
        __syncthreads();
    }

    // ---- phase 3: PV, thread = dim, split tokens across two halves ----
    const int d = t & 127;
    const int half = t >> 7;
    const int j0 = half * 128;
    float acc[GS];
#pragma unroll
    for (int g = 0; g < GS; g++) acc[g] = 0.f;
    const int jend = min(128, nvalid - j0);
    for (int jj = 0; jj < jend; jj++) {
        const int jt = j0 + jj;
        const float vv = (jt == jpos) ? vnew_s[d] : V[(size_t)jt * HD + d];
#pragma unroll
        for (int g = 0; g < GS; g++) acc[g] += p_s[g][jt] * vv;
    }
    if (half == 1) {
#pragma unroll
        for (int g = 0; g < GS; g++) acc2_s[g][d] = acc[g];
    }
    __syncthreads();
    if (half == 0) {
        float* outp = g_part + (size_t)rc * (GS * HD);
#pragma unroll
        for (int g = 0; g < GS; g++)
            outp[g * HD + d] = acc[g] + acc2_s[g][d];
    }
}

// ============================================================
// Combine split-K partials. grid = (GS, Rr), 128 threads.
// ============================================================
__global__ void attn_combine(const int* __restrict__ cache_seqlens) {
    const int g = blockIdx.x;
    const int r = blockIdx.y;
    const int d = threadIdx.x;
    const int seqlen = cache_seqlens[r];
    const int nc = (seqlen + BSZ - 1) >> 8;

    float M = NEG_INF;
    for (int c = 0; c < nc; c++)
        M = fmaxf(M, g_ml[(r * MB + c) * (GS * 2) + g * 2]);
    float L = 0.f, acc = 0.f;
    for (int c = 0; c < nc; c++) {
        const int rc = r * MB + c;
        const float m = g_ml[rc * (GS * 2) + g * 2 + 0];
        const float l = g_ml[rc * (GS * 2) + g * 2 + 1];
        const float w = __expf(m - M);
        L += l * w;
        acc += w * g_part[(size_t)rc * (GS * HD) + g * HD + d];
    }
    const int b = r >> 2, kvh = r & 3;
    g_attn[(size_t)b * Hdim + (kvh * GS + g) * HD + d] = acc / L;
}

// ============================================================
extern "C" void kernel_launch(void* const* d_in, const int* in_sizes, int n_in,
                              void* d_out, int out_size) {
    const float* hid  = (const float*)d_in[0];
    const float* cosw = (const float*)d_in[1];
    const float* sinw = (const float*)d_in[2];
    const float* q_w  = (const float*)d_in[3];
    const float* q_b  = (const float*)d_in[4];
    const float* k_w  = (const float*)d_in[5];
    const float* k_b  = (const float*)d_in[6];
    const float* v_w  = (const float*)d_in[7];
    const float* v_b  = (const float*)d_in[8];
    const float* o_w  = (const float*)d_in[9];
    const float* k_pool = (const float*)d_in[10];
    const float* v_pool = (const float*)d_in[11];
    const int* block_table   = (const int*)d_in[12];
    const int* cache_seqlens = (const int*)d_in[13];
    float* out = (float*)d_out;

    // QKV projections
    gemv8<<<Hdim, 128>>>(hid, q_w, q_b, nullptr, 0);
    gemv8<<<KVH * HD, 128>>>(hid, k_w, k_b, nullptr, 1);
    gemv8<<<KVH * HD, 128>>>(hid, v_w, v_b, nullptr, 2);
    // RoPE on q and k
    rope_kernel<<<Bb * 32, 128>>>(cosw, sinw);
    // flash-decode partials
    attn_partial<<<dim3(MB, Rr), 256>>>(k_pool, v_pool, block_table, cache_seqlens);
    // combine
    attn_combine<<<dim3(GS, Rr), 128>>>(cache_seqlens);
    // O projection
    gemv8<<<Hdim, 128>>>(nullptr, o_w, nullptr, out, 3);
}